// round 1
// baseline (speedup 1.0000x reference)
#include <cuda_runtime.h>
#include <math.h>

#define LDIM 32
#define HDIM 64

// One warp per sample. Thread t owns output channels {t, t+32}.
// Wc columns live in registers; Hprev (row above) lives in shared;
// the recurrent vector u = h + cV is broadcast via a double-buffered
// shared staging buffer (2 STS + 16 broadcast LDS.128 per step).
__global__ void __launch_bounds__(32) rnn2d_kernel(
    const int*   __restrict__ x,     // (B, 32, 32) int32, values in {0,1}
    const float* __restrict__ Win,   // (2, 64)
    const float* __restrict__ Wc,    // (64, 64)
    const float* __restrict__ bc,    // (64,)
    const float* __restrict__ Wout,  // (64, 2)
    const float* __restrict__ bout,  // (2,)
    float*       __restrict__ out)   // (B,)
{
    const int b  = blockIdx.x;
    const int t  = threadIdx.x;        // 0..31
    const int j0 = t;
    const int j1 = t + 32;

    __shared__ float Hprev[LDIM][HDIM];   // row-above hidden state (physical col order)
    __shared__ float ubuf[2][HDIM];       // double-buffered u = h + cV
    __shared__ int   xrow[2][LDIM];       // current / previous x rows

    // ---- load weights into registers ----
    float wc0[HDIM], wc1[HDIM];
#pragma unroll
    for (int k = 0; k < HDIM; ++k) {
        wc0[k] = Wc[k * HDIM + j0];
        wc1[k] = Wc[k * HDIM + j1];
    }
    const float win00 = Win[j0],        win10 = Win[HDIM + j0];   // Win[d][j0]
    const float win01 = Win[j1],        win11 = Win[HDIM + j1];   // Win[d][j1]
    const float bc0   = bc[j0],         bc1   = bc[j1];
    const float wo00  = Wout[j0 * 2],   wo01  = Wout[j0 * 2 + 1];
    const float wo10  = Wout[j1 * 2],   wo11  = Wout[j1 * 2 + 1];
    const float bo0   = bout[0],        bo1   = bout[1];

#pragma unroll
    for (int c = 0; c < LDIM; ++c) {
        Hprev[c][j0] = 0.0f;
        Hprev[c][j1] = 0.0f;
    }

    const int* xb = x + b * LDIM * LDIM;
    float logp_sum = 0.0f;

    for (int i = 0; i < LDIM; ++i) {
        __syncwarp();                       // prior row done reading xrow[i&1]
        xrow[i & 1][t] = xb[i * LDIM + t];
        __syncwarp();

        const int dir  = (i & 1) ? -1 : 1;  // boustrophedon
        const int cur  = i & 1;
        const int prev = cur ^ 1;

        float h0 = 0.0f, h1 = 0.0f;         // per-row scan carry (this thread's channels)

        for (int jj = 0; jj < LDIM; ++jj) {
            const int c = (i & 1) ? (LDIM - 1 - jj) : jj;   // physical column
            const int p = jj & 1;

            // u = h + carry-from-above
            const float u0 = h0 + Hprev[c][j0];
            const float u1 = h1 + Hprev[c][j1];
            ubuf[p][j0] = u0;
            ubuf[p][j1] = u1;

            const int xC = xrow[cur][c];
            const int xL = (jj > 0) ? xrow[cur][c - dir] : 0;
            const int xU = (i  > 0) ? xrow[prev][c]      : 0;

            __syncwarp();

            // base = bc + newR @ Win  (newR = one-hot(left-in-scan) + one-hot(above))
            float r0 = bc0, r1 = bc1;
            if (jj > 0) { r0 += xL ? win10 : win00;  r1 += xL ? win11 : win01; }
            if (i  > 0) { r0 += xU ? win10 : win00;  r1 += xU ? win11 : win01; }

            // 64-wide matvec against register-resident Wc columns
            float a0 = r0,  a1 = r1,  a2 = 0.0f, a3 = 0.0f;
            const float4* up = (const float4*)ubuf[p];
#pragma unroll
            for (int k = 0; k < HDIM / 4; ++k) {
                const float4 uv = up[k];
                a0 += uv.x * wc0[4 * k    ];  a1 += uv.x * wc1[4 * k    ];
                a2 += uv.y * wc0[4 * k + 1];  a3 += uv.y * wc1[4 * k + 1];
                a0 += uv.z * wc0[4 * k + 2];  a1 += uv.z * wc1[4 * k + 2];
                a2 += uv.w * wc0[4 * k + 3];  a3 += uv.w * wc1[4 * k + 3];
            }
            const float s0 = a0 + a2;
            const float s1 = a1 + a3;

            // elu (alpha = 1): x>0 ? x : expm1(x)
            const float nh0 = (s0 > 0.0f) ? s0 : expm1f(fminf(s0, 0.0f));
            const float nh1 = (s1 > 0.0f) ? s1 : expm1f(fminf(s1, 0.0f));

            // logits = newH @ Wout + bout  (warp reduction over channels)
            float z0 = nh0 * wo00 + nh1 * wo10;
            float z1 = nh0 * wo01 + nh1 * wo11;
#pragma unroll
            for (int off = 16; off > 0; off >>= 1) {
                z0 += __shfl_xor_sync(0xffffffffu, z0, off);
                z1 += __shfl_xor_sync(0xffffffffu, z1, off);
            }
            z0 += bo0;
            z1 += bo1;

            const float m   = fmaxf(z0, z1);
            const float lse = m + logf(expf(z0 - m) + expf(z1 - m));
            float lp = (xC ? z1 : z0) - lse;
            if (isnan(lp)) lp = -35.0f;
            logp_sum += lp;

            // write back state
            Hprev[c][j0] = nh0;
            Hprev[c][j1] = nh1;
            h0 = nh0;
            h1 = nh1;
        }
    }

    if (t == 0) out[b] = 0.5f * logp_sum;
}

extern "C" void kernel_launch(void* const* d_in, const int* in_sizes, int n_in,
                              void* d_out, int out_size) {
    const int*   x    = (const int*)  d_in[0];
    const float* Win  = (const float*)d_in[1];
    const float* Wc   = (const float*)d_in[2];
    const float* bc   = (const float*)d_in[3];
    const float* Wout = (const float*)d_in[4];
    const float* bout = (const float*)d_in[5];
    float* out = (float*)d_out;

    const int B = in_sizes[0] / (LDIM * LDIM);
    rnn2d_kernel<<<B, 32>>>(x, Win, Wc, bc, Wout, bout, out);
}

// round 2
// speedup vs baseline: 2.0572x; 2.0572x over previous
#include <cuda_runtime.h>
#include <math.h>

#define LDIM 32
#define HDIM 64

typedef unsigned long long ull;

__device__ __forceinline__ ull pack2(float lo, float hi) {
    ull r; asm("mov.b64 %0, {%1, %2};" : "=l"(r) : "f"(lo), "f"(hi)); return r;
}
__device__ __forceinline__ float2 unpack2(ull v) {
    float2 r; asm("mov.b64 {%0, %1}, %2;" : "=f"(r.x), "=f"(r.y) : "l"(v)); return r;
}
#define FMA2(d, a, b, c) \
    asm("fma.rn.f32x2 %0, %1, %2, %3;" : "=l"(d) : "l"(a), "l"(b), "l"(c))

// One warp per sample. Thread t owns output channels {t, t+32}.
// Wc columns live in registers as packed f32x2 pairs (along k).
// The recurrent vector u = h + carry-from-above is broadcast through a
// double-buffered smem staging buffer. The log-softmax warp reduction of
// step j-1 is deferred and overlapped with the matvec of step j.
__global__ void __launch_bounds__(32) rnn2d_kernel(
    const int*   __restrict__ x,     // (B, 32, 32) int32, values in {0,1}
    const float* __restrict__ Win,   // (2, 64)
    const float* __restrict__ Wc,    // (64, 64)
    const float* __restrict__ bc,    // (64,)
    const float* __restrict__ Wout,  // (64, 2)
    const float* __restrict__ bout,  // (2,)
    float*       __restrict__ out)   // (B,)
{
    const int b = blockIdx.x;
    const int t = threadIdx.x;          // 0..31

    __shared__ float2 Hprev2[LDIM][LDIM];  // [col][t] — thread-private columns
    __shared__ float  ubuf[2][HDIM];       // double-buffered u (k-order)
    __shared__ int    xrow[2][LDIM];       // current / previous x rows

    // ---- pack Wc columns j0=t, j1=t+32 into f32x2 register pairs along k ----
    ull wcp0[HDIM / 2], wcp1[HDIM / 2];
#pragma unroll
    for (int k = 0; k < HDIM / 2; ++k) {
        wcp0[k] = pack2(Wc[(2 * k) * HDIM + t],      Wc[(2 * k + 1) * HDIM + t]);
        wcp1[k] = pack2(Wc[(2 * k) * HDIM + t + 32], Wc[(2 * k + 1) * HDIM + t + 32]);
    }
    const float win00 = Win[t],        win10 = Win[HDIM + t];
    const float win01 = Win[t + 32],   win11 = Win[HDIM + t + 32];
    const float bc0   = bc[t],         bc1   = bc[t + 32];
    const float wo00  = Wout[t * 2],         wo01 = Wout[t * 2 + 1];
    const float wo10  = Wout[(t + 32) * 2],  wo11 = Wout[(t + 32) * 2 + 1];
    const float bo0   = bout[0],       bo1   = bout[1];

#pragma unroll
    for (int c = 0; c < LDIM; ++c) Hprev2[c][t] = make_float2(0.0f, 0.0f);

    const int* xb = x + b * LDIM * LDIM;

    float logp = 0.0f;
    float pendScale = 0.0f;             // 0 until the first step's z is pending
    float pz0 = 0.0f, pz1 = 0.0f;       // deferred per-thread logit partials
    int   pxC = 0;

    float2 hp = Hprev2[0][t];           // prefetched carry-from-above (zeros)

    for (int i = 0; i < LDIM; ++i) {
        __syncwarp();
        xrow[i & 1][t] = xb[i * LDIM + t];
        // (visibility of xrow provided by the per-step syncwarp below)

        const int dir  = (i & 1) ? -1 : 1;
        const int cur  = i & 1;
        const int prev = cur ^ 1;

        float h0 = 0.0f, h1 = 0.0f;     // row-scan carry

#pragma unroll 2
        for (int jj = 0; jj < LDIM; ++jj) {
            const int c = (i & 1) ? (LDIM - 1 - jj) : jj;
            const int p = jj & 1;

            // u = h + carry-from-above (hp was prefetched)
            const float u0 = h0 + hp.x;
            const float u1 = h1 + hp.y;
            ubuf[p][t]      = u0;
            ubuf[p][t + 32] = u1;

            __syncwarp();

            const int xC = xrow[cur][c];
            const int xL = (jj > 0) ? xrow[cur][c - dir] : 0;
            const int xU = (i  > 0) ? xrow[prev][c]      : 0;

            // ---- deferred reduction of previous step (overlaps matvec) ----
            float z0 = pz0, z1 = pz1;
#pragma unroll
            for (int off = 16; off > 0; off >>= 1) {
                z0 += __shfl_xor_sync(0xffffffffu, z0, off);
                z1 += __shfl_xor_sync(0xffffffffu, z1, off);
            }
            z0 += bo0;
            z1 += bo1;
            const float m   = fmaxf(z0, z1);
            const float lse = m + __logf(__expf(z0 - m) + __expf(z1 - m));
            float lp = (pxC ? z1 : z0) - lse;
            if (lp != lp) lp = -35.0f;
            logp += pendScale * lp;

            // ---- base = bc + newR @ Win ----
            float r0 = bc0, r1 = bc1;
            if (jj > 0) { r0 += xL ? win10 : win00;  r1 += xL ? win11 : win01; }
            if (i  > 0) { r0 += xU ? win10 : win00;  r1 += xU ? win11 : win01; }

            // ---- 64-wide matvec with packed f32x2 FMAs ----
            ull a00 = 0, a01 = 0, a10 = 0, a11 = 0;
            const ulonglong2* up = (const ulonglong2*)ubuf[p];
#pragma unroll
            for (int k = 0; k < HDIM / 4; ++k) {
                const ulonglong2 uv = up[k];       // pairs (4k,4k+1) and (4k+2,4k+3)
                FMA2(a00, uv.x, wcp0[2 * k],     a00);
                FMA2(a10, uv.x, wcp1[2 * k],     a10);
                FMA2(a01, uv.y, wcp0[2 * k + 1], a01);
                FMA2(a11, uv.y, wcp1[2 * k + 1], a11);
            }
            const float2 f00 = unpack2(a00), f01 = unpack2(a01);
            const float2 f10 = unpack2(a10), f11 = unpack2(a11);
            const float s0 = r0 + (f00.x + f00.y) + (f01.x + f01.y);
            const float s1 = r1 + (f10.x + f10.y) + (f11.x + f11.y);

            // elu (alpha = 1), fast-math exp
            const float nh0 = (s0 > 0.0f) ? s0 : (__expf(s0) - 1.0f);
            const float nh1 = (s1 > 0.0f) ? s1 : (__expf(s1) - 1.0f);

            // stash this step's logit partials for the deferred reduction
            pz0 = nh0 * wo00 + nh1 * wo10;
            pz1 = nh0 * wo01 + nh1 * wo11;
            pxC = xC;
            pendScale = 1.0f;

            // writeback + prefetch next carry-from-above
            Hprev2[c][t] = make_float2(nh0, nh1);
            const int cn = (jj < LDIM - 1) ? (c + dir) : c;  // row end: next row starts at same col
            hp = Hprev2[cn][t];

            h0 = nh0;
            h1 = nh1;
        }
    }

    // ---- flush the final pending step ----
    {
        float z0 = pz0, z1 = pz1;
#pragma unroll
        for (int off = 16; off > 0; off >>= 1) {
            z0 += __shfl_xor_sync(0xffffffffu, z0, off);
            z1 += __shfl_xor_sync(0xffffffffu, z1, off);
        }
        z0 += bo0;
        z1 += bo1;
        const float m   = fmaxf(z0, z1);
        const float lse = m + __logf(__expf(z0 - m) + __expf(z1 - m));
        float lp = (pxC ? z1 : z0) - lse;
        if (lp != lp) lp = -35.0f;
        logp += lp;
    }

    if (t == 0) out[b] = 0.5f * logp;
}

extern "C" void kernel_launch(void* const* d_in, const int* in_sizes, int n_in,
                              void* d_out, int out_size) {
    const int*   x    = (const int*)  d_in[0];
    const float* Win  = (const float*)d_in[1];
    const float* Wc   = (const float*)d_in[2];
    const float* bc   = (const float*)d_in[3];
    const float* Wout = (const float*)d_in[4];
    const float* bout = (const float*)d_in[5];
    float* out = (float*)d_out;

    const int B = in_sizes[0] / (LDIM * LDIM);
    rnn2d_kernel<<<B, 32>>>(x, Win, Wc, bc, Wout, bout, out);
}